// round 3
// baseline (speedup 1.0000x reference)
#include <cuda_runtime.h>
#include <cstdint>

#define BS   16
#define MGT  256
#define NC   80
#define NA   3
#define S0   160
#define S1   80
#define S2   40
#define NGT  33600
#define OFF1 25600
#define OFF2 32000

// Output float offsets (row-major flatten of the 5-tuple, all float32)
#define BASE_TXY 0ull
#define BASE_WH  3225600ull
#define BASE_SC  6451200ull
#define BASE_ANC 135475200ull
#define BASE_MSK 138700800ull
#define N_SC4    32256000    // 129,024,000 floats / 4

// Scratch (no allocations allowed)
__device__ __align__(16) int g_count[BS * NGT];
__device__ int   g_claim[BS * NGT];
__device__ int   g_topk[3 * BS * MGT * 3];     // global cell idx of each gt's top-3
__device__ float g_gcxy[3 * BS * MGT * 2];     // gt_cxy / stride, per layer
__device__ float g_gwh [3 * BS * MGT * 2];     // gt_wh  / stride, per layer
__device__ int   g_amask[3 * BS * MGT];        // 3-bit anchor wh-ratio gate per (l,gt)
__device__ int   g_labn[BS * MGT];             // normalized int32 labels
__device__ float g_ancs[9 * 2];                // anc_wh / stride
__device__ int   g_is64;

// ---------------------------------------------------------------------------
// Pure write stream: zero the 516 MB scores region + the claim counts.
__global__ __launch_bounds__(256)
void zero_all(float* __restrict__ out) {
    unsigned i = blockIdx.x * blockDim.x + threadIdx.x;
    if (i < N_SC4)
        ((float4*)(out + BASE_SC))[i] = make_float4(0.f, 0.f, 0.f, 0.f);
    if (i < BS * NGT / 4)
        ((int4*)g_count)[i] = make_int4(0, 0, 0, 0);
}

// Detect int64-vs-int32 labels; precompute anchor/stride table.
__global__ void detect_kernel(const int* __restrict__ lab32,
                              const float* __restrict__ anc_whs,
                              const float* __restrict__ strides) {
    __shared__ int acc;
    if (threadIdx.x == 0) acc = 0;
    __syncthreads();
    int v = 0;
    for (int t = threadIdx.x; t < BS * MGT; t += blockDim.x)
        v |= lab32[2 * t + 1];
    if (v) atomicOr(&acc, 1);
    __syncthreads();
    if (threadIdx.x == 0) g_is64 = (acc == 0) ? 1 : 0;
    if (threadIdx.x < 9) {
        float st = strides[threadIdx.x / 3];
        g_ancs[2 * threadIdx.x]     = __fdiv_rn(anc_whs[2 * threadIdx.x],     st);
        g_ancs[2 * threadIdx.x + 1] = __fdiv_rn(anc_whs[2 * threadIdx.x + 1], st);
    }
}

// ---------------------------------------------------------------------------
// One thread per (layer, b, m): all per-gt precompute + top-3 claim scatter.
__global__ void claim_kernel(const float* __restrict__ gt_cxy,
                             const float* __restrict__ gt_wh,
                             const int*   __restrict__ lab32,
                             const float* __restrict__ mask_gt,
                             const float* __restrict__ strides) {
    int idx = blockIdx.x * blockDim.x + threadIdx.x;
    if (idx >= 3 * BS * MGT) return;
    int l  = idx / (BS * MGT);
    int bm = idx - l * (BS * MGT);
    int b  = bm / MGT;
    int m  = bm - b * MGT;

    int s   = (l == 0) ? S0 : (l == 1) ? S1 : S2;
    int off = (l == 0) ? 0  : (l == 1) ? OFF1 : OFF2;
    float stride = strides[l];

    if (l == 0)
        g_labn[bm] = g_is64 ? lab32[2 * bm] : lab32[bm];

    float gcx = __fdiv_rn(gt_cxy[2 * bm],     stride);
    float gcy = __fdiv_rn(gt_cxy[2 * bm + 1], stride);
    g_gcxy[2 * idx]     = gcx;
    g_gcxy[2 * idx + 1] = gcy;

    float tw = __fdiv_rn(gt_wh[2 * bm],     stride);
    float th = __fdiv_rn(gt_wh[2 * bm + 1], stride);
    g_gwh[2 * idx]     = tw;
    g_gwh[2 * idx + 1] = th;

    // per-anchor wh-ratio gate (cell independent)
    int amask = 0;
    #pragma unroll
    for (int j = 0; j < NA; j++) {
        float aw = g_ancs[(l * NA + j) * 2];
        float ah = g_ancs[(l * NA + j) * 2 + 1];
        float rw = __fdiv_rn(tw, aw);
        float rh = __fdiv_rn(th, ah);
        float mr = fmaxf(fmaxf(rw, __fdiv_rn(1.0f, rw)),
                         fmaxf(rh, __fdiv_rn(1.0f, rh)));
        if (mr < 4.0f) amask |= (1 << j);
    }
    g_amask[idx] = amask;

    // analytic top-3 nearest cells: 5x5 window around floor(gcxy)
    int x0 = (int)floorf(gcx); x0 = min(max(x0, 0), s - 1);
    int y0 = (int)floorf(gcy); y0 = min(max(y0, 0), s - 1);
    int xs = max(0, x0 - 2), xe = min(s - 1, x0 + 2);
    int ys = max(0, y0 - 2), ye = min(s - 1, y0 + 2);

    float d0 = 1e30f, d1 = 1e30f, d2 = 1e30f;
    int   i0 = 0,     i1 = 0,     i2 = 0;
    for (int yy = ys; yy <= ye; yy++) {
        float ady = fabsf((float)yy + 0.5f - gcy);
        for (int xx = xs; xx <= xe; xx++) {
            float d = fabsf((float)xx + 0.5f - gcx) + ady;
            int gi = yy * s + xx;
            if (d < d0)      { d2 = d1; i2 = i1; d1 = d0; i1 = i0; d0 = d; i0 = gi; }
            else if (d < d1) { d2 = d1; i2 = i1; d1 = d;  i1 = gi; }
            else if (d < d2) { d2 = d;  i2 = gi; }
        }
    }
    int gA = off + i0, gB = off + i1, gC = off + i2;
    int* tk = g_topk + ((l * BS + b) * MGT + m) * 3;
    tk[0] = gA; tk[1] = gB; tk[2] = gC;

    if (mask_gt[bm] != 0.0f) {
        atomicAdd(&g_count[b * NGT + gA], 1); g_claim[b * NGT + gA] = m;
        atomicAdd(&g_count[b * NGT + gB], 1); g_claim[b * NGT + gB] = m;
        atomicAdd(&g_count[b * NGT + gC], 1); g_claim[b * NGT + gC] = m;
    }
}

// ---------------------------------------------------------------------------
// One thread per (b, cell): warp-cooperative resolution + all outputs,
// including the scatter of the one-hot 1.0s into the pre-zeroed scores.
__global__ __launch_bounds__(256)
void resolve_kernel(const float* __restrict__ mask_gt,
                    float* __restrict__ out) {
    int idx = blockIdx.x * blockDim.x + threadIdx.x;   // grid covers exactly BS*NGT
    int b  = idx / NGT;
    int gg = idx - b * NGT;

    int l, s, off;
    if (gg < OFF1)      { l = 0; s = S0; off = 0;    }
    else if (gg < OFF2) { l = 1; s = S1; off = OFF1; }
    else                { l = 2; s = S2; off = OFF2; }
    int lg = gg - off;
    int gx = lg % s;
    int gy = lg / s;

    // warp-uniform: NGT, OFF1, OFF2 are multiples of 32
    int lb = (l * BS + b) * MGT;
    const float2* gcxy = (const float2*)g_gcxy + lb;

    int c   = g_count[idx];
    int tgt = 0, fgv = 0;
    if (c == 1) { tgt = g_claim[idx]; fgv = 1; }

    // warp-cooperative argmax for conflicted cells (c > 1)
    float cx = (float)gx + 0.5f, cy = (float)gy + 0.5f;
    int myl = threadIdx.x & 31;
    unsigned conf = __ballot_sync(0xffffffffu, c > 1);
    while (conf) {
        int lsrc = __ffs(conf) - 1; conf &= conf - 1;
        float ccx = __shfl_sync(0xffffffffu, cx, lsrc);
        float ccy = __shfl_sync(0xffffffffu, cy, lsrc);
        float best = -1.0f; int mi = 0;
        for (int m = myl; m < MGT; m += 32) {
            float2 gc = __ldg(&gcxy[m]);
            float d = fabsf(ccx - gc.x) + fabsf(ccy - gc.y);
            if (d > best) { best = d; mi = m; }
        }
        #pragma unroll
        for (int o = 16; o; o >>= 1) {
            float ob = __shfl_down_sync(0xffffffffu, best, o);
            int   oi = __shfl_down_sync(0xffffffffu, mi,   o);
            if (ob > best || (ob == best && oi < mi)) { best = ob; mi = oi; }
        }
        mi = __shfl_sync(0xffffffffu, mi, 0);   // first-max == argmax semantics
        if (myl == lsrc) {
            const int* tk = g_topk + (lb + mi) * 3;
            if (mask_gt[b * MGT + mi] != 0.0f &&
                (tk[0] == gg || tk[1] == gg || tk[2] == gg)) { tgt = mi; fgv = 1; }
        }
    }

    float2 tcxy = __ldg(&gcxy[tgt]);
    float2 twh  = __ldg(&((const float2*)g_gwh)[lb + tgt]);
    int lab     = g_labn[b * MGT + tgt];
    int amask   = g_amask[lb + tgt];
    float tx = tcxy.x - (float)gx;
    float ty = tcxy.y - (float)gy;

    float2* out_txy = (float2*)(out + BASE_TXY);
    float2* out_wh  = (float2*)(out + BASE_WH);
    float2* out_anc = (float2*)(out + BASE_ANC);
    float*  out_msk = out + BASE_MSK;
    float*  out_sc  = out + BASE_SC;

    #pragma unroll
    for (int j = 0; j < NA; j++) {
        size_t o = ((size_t)(b * NA + j)) * NGT + gg;
        out_txy[o] = make_float2(tx, ty);
        out_wh[o]  = twh;
        out_anc[o] = ((const float2*)g_ancs)[l * NA + j];
        out_msk[o] = (fgv && ((amask >> j) & 1)) ? 1.0f : 0.0f;
        out_sc[o * NC + lab] = 1.0f;             // one-hot scatter into zeroed region
    }
}

// ---------------------------------------------------------------------------
extern "C" void kernel_launch(void* const* d_in, const int* in_sizes, int n_in,
                              void* d_out, int out_size) {
    const float* anc     = (const float*)d_in[0];
    // d_in[1..3] = grids (recomputed analytically, unused)
    const int*   lab32   = (const int*)d_in[4];
    const float* gt_cxy  = (const float*)d_in[5];
    const float* gt_wh   = (const float*)d_in[6];
    const float* strides = (const float*)d_in[7];
    const float* mask_gt = (const float*)d_in[8];
    float* out = (float*)d_out;

    zero_all<<<(N_SC4 + 255) / 256, 256>>>(out);
    detect_kernel<<<1, 256>>>(lab32, anc, strides);
    claim_kernel<<<(3 * BS * MGT + 255) / 256, 256>>>(gt_cxy, gt_wh, lab32,
                                                      mask_gt, strides);
    resolve_kernel<<<BS * NGT / 256, 256>>>(mask_gt, out);
}

// round 5
// speedup vs baseline: 1.5496x; 1.5496x over previous
#include <cuda_runtime.h>
#include <cstdint>

#define BS   16
#define MGT  256
#define NC   80
#define NA   3
#define S0   160
#define S1   80
#define S2   40
#define NGT  33600
#define OFF1 25600
#define OFF2 32000
#define NTILE 132            // ceil(NGT/256)

// Output float offsets (row-major flatten of the 5-tuple, all float32)
#define BASE_TXY 0ull
#define BASE_WH  3225600ull
#define BASE_SC  6451200ull
#define BASE_ANC 135475200ull
#define BASE_MSK 138700800ull

// Scratch (no allocations allowed)
__device__ __align__(16) int g_count[BS * NGT];
__device__ int   g_claim[BS * NGT];
__device__ int   g_topk[3 * BS * MGT * 3];     // global cell idx of each gt's top-3
__device__ float g_gcxy[3 * BS * MGT * 2];     // gt_cxy / stride, per layer
__device__ float g_gwh [3 * BS * MGT * 2];     // gt_wh  / stride, per layer
__device__ int   g_amask[3 * BS * MGT];        // 3-bit anchor wh-ratio gate per (l,gt)
__device__ int   g_labn[BS * MGT];             // normalized int32 labels
__device__ float g_ancs[9 * 2];                // anc_wh / stride
__device__ int   g_is64;

// ---------------------------------------------------------------------------
// Zero claim counts; block 0 also detects label width + builds anchor table.
__global__ __launch_bounds__(256)
void prep_kernel(const int* __restrict__ lab32,
                 const float* __restrict__ anc_whs,
                 const float* __restrict__ strides) {
    int i = blockIdx.x * blockDim.x + threadIdx.x;
    if (i < BS * NGT / 4)
        ((int4*)g_count)[i] = make_int4(0, 0, 0, 0);
    if (blockIdx.x == 0) {
        __shared__ int acc;
        if (threadIdx.x == 0) acc = 0;
        __syncthreads();
        int v = 0;
        for (int t = threadIdx.x; t < BS * MGT; t += blockDim.x)
            v |= lab32[2 * t + 1];
        if (v) atomicOr(&acc, 1);
        __syncthreads();
        if (threadIdx.x == 0) g_is64 = (acc == 0) ? 1 : 0;
        if (threadIdx.x < 9) {
            float st = strides[threadIdx.x / 3];
            g_ancs[2 * threadIdx.x]     = __fdiv_rn(anc_whs[2 * threadIdx.x],     st);
            g_ancs[2 * threadIdx.x + 1] = __fdiv_rn(anc_whs[2 * threadIdx.x + 1], st);
        }
    }
}

// ---------------------------------------------------------------------------
// One thread per (layer, b, m): per-gt precompute + top-3 claim scatter.
__global__ void claim_kernel(const float* __restrict__ gt_cxy,
                             const float* __restrict__ gt_wh,
                             const int*   __restrict__ lab32,
                             const float* __restrict__ mask_gt,
                             const float* __restrict__ strides) {
    int idx = blockIdx.x * blockDim.x + threadIdx.x;
    if (idx >= 3 * BS * MGT) return;
    int l  = idx / (BS * MGT);
    int bm = idx - l * (BS * MGT);
    int b  = bm / MGT;
    int m  = bm - b * MGT;

    int s   = (l == 0) ? S0 : (l == 1) ? S1 : S2;
    int off = (l == 0) ? 0  : (l == 1) ? OFF1 : OFF2;
    float stride = strides[l];

    if (l == 0)
        g_labn[bm] = g_is64 ? lab32[2 * bm] : lab32[bm];

    float gcx = __fdiv_rn(gt_cxy[2 * bm],     stride);
    float gcy = __fdiv_rn(gt_cxy[2 * bm + 1], stride);
    g_gcxy[2 * idx]     = gcx;
    g_gcxy[2 * idx + 1] = gcy;

    float tw = __fdiv_rn(gt_wh[2 * bm],     stride);
    float th = __fdiv_rn(gt_wh[2 * bm + 1], stride);
    g_gwh[2 * idx]     = tw;
    g_gwh[2 * idx + 1] = th;

    int amask = 0;
    #pragma unroll
    for (int j = 0; j < NA; j++) {
        float aw = g_ancs[(l * NA + j) * 2];
        float ah = g_ancs[(l * NA + j) * 2 + 1];
        float rw = __fdiv_rn(tw, aw);
        float rh = __fdiv_rn(th, ah);
        float mr = fmaxf(fmaxf(rw, __fdiv_rn(1.0f, rw)),
                         fmaxf(rh, __fdiv_rn(1.0f, rh)));
        if (mr < 4.0f) amask |= (1 << j);
    }
    g_amask[idx] = amask;

    int x0 = (int)floorf(gcx); x0 = min(max(x0, 0), s - 1);
    int y0 = (int)floorf(gcy); y0 = min(max(y0, 0), s - 1);
    int xs = max(0, x0 - 2), xe = min(s - 1, x0 + 2);
    int ys = max(0, y0 - 2), ye = min(s - 1, y0 + 2);

    float d0 = 1e30f, d1 = 1e30f, d2 = 1e30f;
    int   i0 = 0,     i1 = 0,     i2 = 0;
    for (int yy = ys; yy <= ye; yy++) {
        float ady = fabsf((float)yy + 0.5f - gcy);
        for (int xx = xs; xx <= xe; xx++) {
            float d = fabsf((float)xx + 0.5f - gcx) + ady;
            int gi = yy * s + xx;
            if (d < d0)      { d2 = d1; i2 = i1; d1 = d0; i1 = i0; d0 = d; i0 = gi; }
            else if (d < d1) { d2 = d1; i2 = i1; d1 = d;  i1 = gi; }
            else if (d < d2) { d2 = d;  i2 = gi; }
        }
    }
    int gA = off + i0, gB = off + i1, gC = off + i2;
    int* tk = g_topk + ((l * BS + b) * MGT + m) * 3;
    tk[0] = gA; tk[1] = gB; tk[2] = gC;

    if (mask_gt[bm] != 0.0f) {
        atomicAdd(&g_count[b * NGT + gA], 1); g_claim[b * NGT + gA] = m;
        atomicAdd(&g_count[b * NGT + gB], 1); g_claim[b * NGT + gB] = m;
        atomicAdd(&g_count[b * NGT + gC], 1); g_claim[b * NGT + gC] = m;
    }
}

// ---------------------------------------------------------------------------
// Fused: grid (NTILE, BS); block (x,y) owns cells [x*256, x*256+256) of batch y.
// b and the tile base are block-uniform by construction; only the last tile
// is partial (64 cells). Phase 1: resolve + txy/wh/anc/msk, labels -> smem.
// Phase 2: stream the block's 3 contiguous one-hot score slabs.
__global__ __launch_bounds__(256)
void resolve_scores_kernel(const float* __restrict__ mask_gt,
                           float* __restrict__ out) {
    __shared__ int lab_s[256];

    int b   = blockIdx.y;
    int gg0 = blockIdx.x * 256;                        // block-uniform
    int gg  = gg0 + (int)threadIdx.x;
    bool active = (gg < NGT);
    int ggc = active ? gg : NGT - 1;                   // clamp for uniform exec

    int l, s, off;
    if (ggc < OFF1)      { l = 0; s = S0; off = 0;    }
    else if (ggc < OFF2) { l = 1; s = S1; off = OFF1; }
    else                 { l = 2; s = S2; off = OFF2; }
    int lg = ggc - off;
    int gx = lg % s;
    int gy = lg / s;

    int lb = (l * BS + b) * MGT;                       // warp-uniform
    const float2* gcxy = (const float2*)g_gcxy + lb;
    int idx = b * NGT + ggc;

    int c   = g_count[idx];
    int tgt = 0, fgv = 0;
    if (c == 1) { tgt = g_claim[idx]; fgv = 1; }

    // warp-cooperative argmax for conflicted cells (c > 1)
    float cx = (float)gx + 0.5f, cy = (float)gy + 0.5f;
    int myl = threadIdx.x & 31;
    unsigned conf = __ballot_sync(0xffffffffu, c > 1 && active);
    while (conf) {
        int lsrc = __ffs(conf) - 1; conf &= conf - 1;
        float ccx = __shfl_sync(0xffffffffu, cx, lsrc);
        float ccy = __shfl_sync(0xffffffffu, cy, lsrc);
        float best = -1.0f; int mi = 0;
        for (int m = myl; m < MGT; m += 32) {
            float2 gc = __ldg(&gcxy[m]);
            float d = fabsf(ccx - gc.x) + fabsf(ccy - gc.y);
            if (d > best) { best = d; mi = m; }
        }
        #pragma unroll
        for (int o = 16; o; o >>= 1) {
            float ob = __shfl_down_sync(0xffffffffu, best, o);
            int   oi = __shfl_down_sync(0xffffffffu, mi,   o);
            if (ob > best || (ob == best && oi < mi)) { best = ob; mi = oi; }
        }
        mi = __shfl_sync(0xffffffffu, mi, 0);          // first-max == argmax
        if (myl == lsrc) {
            const int* tk = g_topk + (lb + mi) * 3;
            if (mask_gt[b * MGT + mi] != 0.0f &&
                (tk[0] == ggc || tk[1] == ggc || tk[2] == ggc)) { tgt = mi; fgv = 1; }
        }
    }

    float2 tcxy = __ldg(&gcxy[tgt]);
    float2 twh  = __ldg(&((const float2*)g_gwh)[lb + tgt]);
    int lab     = g_labn[b * MGT + tgt];
    int amask   = g_amask[lb + tgt];
    float tx = tcxy.x - (float)gx;
    float ty = tcxy.y - (float)gy;

    lab_s[threadIdx.x] = lab;

    if (active) {
        float2* out_txy = (float2*)(out + BASE_TXY);
        float2* out_wh  = (float2*)(out + BASE_WH);
        float2* out_anc = (float2*)(out + BASE_ANC);
        float*  out_msk = out + BASE_MSK;
        #pragma unroll
        for (int j = 0; j < NA; j++) {
            size_t o = ((size_t)(b * NA + j)) * NGT + gg;
            out_txy[o] = make_float2(tx, ty);
            out_wh[o]  = twh;
            out_anc[o] = ((const float2*)g_ancs)[l * NA + j];
            out_msk[o] = (fgv && ((amask >> j) & 1)) ? 1.0f : 0.0f;
        }
    }

    __syncthreads();

    // Phase 2: scores — contiguous per-(b,j) slab, rows*20 float4.
    int rows  = min(256, NGT - gg0);
    int total = rows * 20;
    #pragma unroll 1
    for (int j = 0; j < NA; j++) {
        float4* slab = (float4*)(out + BASE_SC +
                       (((size_t)(b * NA + j)) * NGT + gg0) * NC);
        for (int p = threadIdx.x; p < total; p += 256) {
            int cell = p / 20;
            int c4   = p - 20 * cell;
            int lb2  = lab_s[cell];
            int base = c4 * 4;
            float4 v;
            v.x = (lb2 == base)     ? 1.0f : 0.0f;
            v.y = (lb2 == base + 1) ? 1.0f : 0.0f;
            v.z = (lb2 == base + 2) ? 1.0f : 0.0f;
            v.w = (lb2 == base + 3) ? 1.0f : 0.0f;
            slab[p] = v;
        }
    }
}

// ---------------------------------------------------------------------------
extern "C" void kernel_launch(void* const* d_in, const int* in_sizes, int n_in,
                              void* d_out, int out_size) {
    const float* anc     = (const float*)d_in[0];
    // d_in[1..3] = grids (recomputed analytically, unused)
    const int*   lab32   = (const int*)d_in[4];
    const float* gt_cxy  = (const float*)d_in[5];
    const float* gt_wh   = (const float*)d_in[6];
    const float* strides = (const float*)d_in[7];
    const float* mask_gt = (const float*)d_in[8];
    float* out = (float*)d_out;

    prep_kernel<<<(BS * NGT / 4 + 255) / 256, 256>>>(lab32, anc, strides);
    claim_kernel<<<(3 * BS * MGT + 255) / 256, 256>>>(gt_cxy, gt_wh, lab32,
                                                      mask_gt, strides);
    dim3 grid(NTILE, BS);
    resolve_scores_kernel<<<grid, 256>>>(mask_gt, out);
}